// round 16
// baseline (speedup 1.0000x reference)
#include <cuda_runtime.h>
#include <cuda_bf16.h>
#include <cstdint>

// CALayer SE, single-pass persistent pipelined kernel, warp-specialized.
// R5 memory structure (depth-1 L2 retention — the only validated-clean one)
// but the serial tail (gate + means + MLP) runs on WARP 0 ONLY, concurrently
// with warps 1-7's DRAM reads of the next chunk, instead of after them.
// 1024 co-resident blocks (LB(256,7): 7x148=1036 slots), 16KB chunk/batch.
// Round b: [all warps] load chunk b (.ca), warp-reduce -> sred[wid]
//          [warp 0]   gate(b-1): spin(~0), means+MLP in registers -> sscale
//          __syncthreads
//          [tid 0]    publish sum(b); [all] scale chunk b-1 (L2 hit), st.cs
//          __syncthreads
// Counters self-reset -> single kernel launch. DRAM traffic = 537MB.

#define BATCH 16
#define CHAN 256
#define CR 16
#define HW 16384               // floats per plane
#define PLANE_F4 (HW/4)        // 4096
#define QF4 (PLANE_F4/4)       // 1024 float4 per quarter chunk
#define NBLK 1024
#define TPB 256

__device__ float g_part[BATCH * CHAN * 4];
__device__ int   g_cnt[BATCH];
__device__ int   g_done[BATCH];

__device__ __forceinline__ void stcs4(float4* p, float4 v) {
    asm volatile("st.global.cs.v4.f32 [%0], {%1,%2,%3,%4};"
                 :: "l"(p), "f"(v.x), "f"(v.y), "f"(v.z), "f"(v.w) : "memory");
}
__device__ __forceinline__ float4 ldcg4(const float4* p) {
    float4 v;
    asm volatile("ld.global.cg.v4.f32 {%0,%1,%2,%3}, [%4];"
                 : "=f"(v.x), "=f"(v.y), "=f"(v.z), "=f"(v.w) : "l"(p));
    return v;
}

__global__ __launch_bounds__(TPB, 7) void fused_se_kernel(
    const float* __restrict__ x, float* __restrict__ out,
    const float* __restrict__ w1, const float* __restrict__ b1,
    const float* __restrict__ w2, const float* __restrict__ b2)
{
    __shared__ float sred[8];
    __shared__ float shid[CR];
    __shared__ float sscale;

    const int chan    = blockIdx.x >> 2;   // 0..255
    const int quarter = blockIdx.x & 3;    // 0..3
    const int tid  = threadIdx.x;
    const int lane = tid & 31;
    const int wid  = tid >> 5;
    const size_t qoff = (size_t)quarter * QF4;

    const float4* __restrict__ x4 = reinterpret_cast<const float4*>(x);
    float4* __restrict__ o4 = reinterpret_cast<float4*>(out);

    auto chunk = [&](int b) {
        return x4 + (size_t)((b << 8) | chan) * PLANE_F4 + qoff;
    };
    auto ochunk = [&](int b) {
        return o4 + (size_t)((b << 8) | chan) * PLANE_F4 + qoff;
    };

    // warp 0 only: gate on batch b, compute means + MLP -> sscale (smem)
    auto gate_mlp_w0 = [&](int b) {
        if (lane == 0) {
            while (atomicAdd(&g_cnt[b], 0) < NBLK) __nanosleep(64);
            __threadfence();
            if (atomicAdd(&g_done[b], 1) == NBLK - 1) {   // last one resets
                atomicExch(&g_cnt[b], 0);
                atomicExch(&g_done[b], 0);
            }
        }
        __syncwarp();
        // means: 8 channels per lane, in registers
        float m[8];
        #pragma unroll
        for (int j = 0; j < 8; j++) {
            const int c = lane + 32 * j;
            const float* q = &g_part[((b << 8) + c) * 4];
            m[j] = (__ldcg(q) + __ldcg(q + 1) + __ldcg(q + 2) + __ldcg(q + 3))
                   * (1.0f / HW);
        }
        // hidden rows: warp-wide dot products
        #pragma unroll
        for (int r = 0; r < CR; r++) {
            float a = 0.f;
            #pragma unroll
            for (int j = 0; j < 8; j++)
                a += __ldg(&w1[r * CHAN + lane + 32 * j]) * m[j];
            #pragma unroll
            for (int o = 16; o; o >>= 1) a += __shfl_xor_sync(0xFFFFFFFF, a, o);
            if (lane == 0) shid[r] = fmaxf(a + __ldg(&b1[r]), 0.f);
        }
        if (lane == 0) {
            float a = __ldg(&b2[chan]);
            #pragma unroll
            for (int r = 0; r < CR; r++)
                a += __ldg(&w2[chan * CR + r]) * shid[r];
            sscale = 1.0f / (1.0f + __expf(-a));
        }
    };

    // ---------- pipelined main loop ----------
    for (int b = 0; b < BATCH; b++) {
        // [all warps] read chunk b, warp-level reduce
        const float4* __restrict__ xp = chunk(b);
        float acc = 0.f;
        #pragma unroll
        for (int i = 0; i < 4; i++) {
            float4 v = xp[tid + i * TPB];          // .ca -> L2 resident
            acc += (v.x + v.y) + (v.z + v.w);
        }
        #pragma unroll
        for (int o = 16; o; o >>= 1) acc += __shfl_xor_sync(0xFFFFFFFF, acc, o);
        if (lane == 0) sred[wid] = acc;

        // [warp 0] serial tail for b-1, overlapped with warps 1-7's loads
        if (wid == 0 && b >= 1) gate_mlp_w0(b - 1);

        __syncthreads();

        // [tid 0] publish block sum of chunk b
        if (tid == 0) {
            float t = 0.f;
            #pragma unroll
            for (int w = 0; w < 8; w++) t += sred[w];
            g_part[((((b << 8) | chan)) << 2) + quarter] = t;
            __threadfence();
            atomicAdd(&g_cnt[b], 1);
        }

        // [all warps] scale chunk b-1 from L2, stream out
        if (b >= 1) {
            const float sc = sscale;
            const float4* __restrict__ xs = chunk(b - 1);
            float4* __restrict__ os = ochunk(b - 1);
            #pragma unroll
            for (int i = 0; i < 4; i++) {
                const int idx = tid + i * TPB;
                float4 v = ldcg4(&xs[idx]);        // L2 hit (1 round old)
                v.x *= sc; v.y *= sc; v.z *= sc; v.w *= sc;
                stcs4(&os[idx], v);
            }
        }
        __syncthreads();   // protect sred / sscale for next round
    }

    // ---------- tail: batch 15 ----------
    if (wid == 0) gate_mlp_w0(BATCH - 1);
    __syncthreads();
    {
        const float sc = sscale;
        const float4* __restrict__ xs = chunk(BATCH - 1);
        float4* __restrict__ os = ochunk(BATCH - 1);
        #pragma unroll
        for (int i = 0; i < 4; i++) {
            const int idx = tid + i * TPB;
            float4 v = ldcg4(&xs[idx]);
            v.x *= sc; v.y *= sc; v.z *= sc; v.w *= sc;
            stcs4(&os[idx], v);
        }
    }
}

extern "C" void kernel_launch(void* const* d_in, const int* in_sizes, int n_in,
                              void* d_out, int out_size) {
    const float* x  = (const float*)d_in[0];
    const float* w1 = (const float*)d_in[1];
    const float* b1 = (const float*)d_in[2];
    const float* w2 = (const float*)d_in[3];
    const float* b2 = (const float*)d_in[4];
    float* out = (float*)d_out;

    fused_se_kernel<<<NBLK, TPB>>>(x, out, w1, b1, w2, b2);
}

// round 17
// speedup vs baseline: 2.1215x; 2.1215x over previous
#include <cuda_runtime.h>
#include <cuda_bf16.h>
#include <cstdint>

// CALayer SE, single-pass persistent pipelined kernel.
// EXACT R5 structure (the validated champion: depth-1 L2 retention,
// publish-before-gate, separate read/gate/scale phases) with self-resetting
// counters so the init kernel and its launch overhead are eliminated.
// 1024 co-resident blocks (LB(256,7): 7x148=1036 slots), each owns a
// quarter-plane (16KB) per batch. Pipeline over 16 batches:
//   round b: read+sum chunk b (.ca -> L2), PUBLISH counter(b);
//            gate(b-1) (published a full round ago -> short spin),
//            means + tiny MLP; re-read chunk b-1 (L2 hit), scale, st.cs.
// Counter self-reset: after passing gate(b), each block increments g_done[b];
// the 1024th zeroes both words -> clean state for the next graph replay.
// DRAM traffic: x read once + out written once = 537MB.

#define BATCH 16
#define CHAN 256
#define CR 16
#define HW 16384               // floats per plane
#define PLANE_F4 (HW/4)        // 4096
#define QF4 (PLANE_F4/4)       // 1024 float4 per quarter chunk
#define NBLK 1024
#define TPB 256

__device__ float g_part[BATCH * CHAN * 4];
__device__ int   g_cnt[BATCH];
__device__ int   g_done[BATCH];

__device__ __forceinline__ void stcs4(float4* p, float4 v) {
    asm volatile("st.global.cs.v4.f32 [%0], {%1,%2,%3,%4};"
                 :: "l"(p), "f"(v.x), "f"(v.y), "f"(v.z), "f"(v.w) : "memory");
}

__global__ __launch_bounds__(TPB, 7) void fused_se_kernel(
    const float* __restrict__ x, float* __restrict__ out,
    const float* __restrict__ w1, const float* __restrict__ b1,
    const float* __restrict__ w2, const float* __restrict__ b2)
{
    __shared__ float sred[8];
    __shared__ float smean[CHAN];
    __shared__ float shid[CR];
    __shared__ float sscale;

    const int chan    = blockIdx.x >> 2;   // 0..255
    const int quarter = blockIdx.x & 3;    // 0..3
    const int tid  = threadIdx.x;
    const int lane = tid & 31;
    const int wid  = tid >> 5;
    const size_t qoff = (size_t)quarter * QF4;

    const float4* __restrict__ x4 = reinterpret_cast<const float4*>(x);
    float4* __restrict__ o4 = reinterpret_cast<float4*>(out);

    auto read_sum = [&](int b) {
        const int p = (b << 8) | chan;
        const float4* __restrict__ xp = x4 + (size_t)p * PLANE_F4 + qoff;
        float acc = 0.f;
        #pragma unroll
        for (int i = 0; i < 4; i++) {
            float4 v = xp[tid + i * TPB];          // .ca -> L2 resident
            acc += (v.x + v.y) + (v.z + v.w);
        }
        #pragma unroll
        for (int o = 16; o; o >>= 1) acc += __shfl_xor_sync(0xFFFFFFFF, acc, o);
        if (lane == 0) sred[wid] = acc;
        __syncthreads();
        if (tid == 0) {
            float t = 0.f;
            #pragma unroll
            for (int w = 0; w < 8; w++) t += sred[w];
            g_part[(p << 2) + quarter] = t;
            __threadfence();
            atomicAdd(&g_cnt[b], 1);
        }
        __syncthreads();   // sred reusable next round
    };

    auto gate_scale = [&](int b) {
        // gate: wait until all 1024 blocks published batch b (1 round slack)
        if (tid == 0) {
            while (atomicAdd(&g_cnt[b], 0) < NBLK) __nanosleep(64);
            __threadfence();
            // self-reset: the last block through zeroes the counters
            if (atomicAdd(&g_done[b], 1) == NBLK - 1) {
                atomicExch(&g_cnt[b], 0);
                atomicExch(&g_done[b], 0);
            }
        }
        __syncthreads();
        // means: tid == channel index
        {
            const int q = ((b << 8) + tid) * 4;
            smean[tid] = (__ldcg(&g_part[q]) + __ldcg(&g_part[q + 1]) +
                          __ldcg(&g_part[q + 2]) + __ldcg(&g_part[q + 3])) * (1.0f / HW);
        }
        __syncthreads();
        // hidden layer: 8 warps x 2 rows
        #pragma unroll
        for (int k = 0; k < 2; k++) {
            const int r = wid * 2 + k;
            float acc = 0.f;
            #pragma unroll
            for (int c = lane; c < CHAN; c += 32)
                acc += __ldg(&w1[r * CHAN + c]) * smean[c];
            #pragma unroll
            for (int o = 16; o; o >>= 1) acc += __shfl_xor_sync(0xFFFFFFFF, acc, o);
            if (lane == 0) shid[r] = fmaxf(acc + __ldg(&b1[r]), 0.f);
        }
        __syncthreads();
        if (tid == 0) {
            float acc = __ldg(&b2[chan]);
            #pragma unroll
            for (int r = 0; r < CR; r++)
                acc += __ldg(&w2[chan * CR + r]) * shid[r];
            sscale = 1.0f / (1.0f + __expf(-acc));
        }
        __syncthreads();
        // re-read from L2, scale, stream out
        const float sc = sscale;
        const int p = (b << 8) | chan;
        const float4* __restrict__ xp = x4 + (size_t)p * PLANE_F4 + qoff;
        float4* __restrict__ op = o4 + (size_t)p * PLANE_F4 + qoff;
        #pragma unroll
        for (int i = 0; i < 4; i++) {
            float4 v = xp[tid + i * TPB];          // L2 hit (1 round old)
            v.x *= sc; v.y *= sc; v.z *= sc; v.w *= sc;
            stcs4(&op[tid + i * TPB], v);
        }
        __syncthreads();
    };

    // ---------- pipelined main loop (publish ALWAYS precedes gate) ----------
    read_sum(0);
    for (int b = 1; b < BATCH; b++) {
        read_sum(b);        // keeps DRAM busy while (b-1) finishes publishing
        gate_scale(b - 1);
    }
    gate_scale(BATCH - 1);
}

extern "C" void kernel_launch(void* const* d_in, const int* in_sizes, int n_in,
                              void* d_out, int out_size) {
    const float* x  = (const float*)d_in[0];
    const float* w1 = (const float*)d_in[1];
    const float* b1 = (const float*)d_in[2];
    const float* w2 = (const float*)d_in[3];
    const float* b2 = (const float*)d_in[4];
    float* out = (float*)d_out;

    fused_se_kernel<<<NBLK, TPB>>>(x, out, w1, b1, w2, b2);
}